// round 2
// baseline (speedup 1.0000x reference)
#include <cuda_runtime.h>
#include <cuda_bf16.h>
#include <stdint.h>

// Problem constants (fixed by reference: B=16, NT=4096, D=512, V=2545)
#define B_  16
#define NT_ 4096
#define D_  512
#define V_  2545
#define D_VEC (D_ / 4)   // 128 float4 per embedding row

// Scratch (no device allocations allowed -> __device__ globals)
__device__ int g_len[B_];
__device__ int g_is64;

// ---------------------------------------------------------------------------
// Kernel 1: (a) probe text dtype layout (int64 vs int32), (b) count valid
// tokens per batch row. One block per batch row, 512 threads.
//
// Probe: interpret the first 32768 int32-word pairs (128 KB x 2 — always in
// bounds for either layout) as little-endian int64. If EVERY pair has
// hi == sign-extension(lo) and lo in [-1, V), the buffer is int64. Real int32
// token data in the hi positions (random in [0,2545)) defeats this with
// probability ~0.
// ---------------------------------------------------------------------------
__global__ void __launch_bounds__(512)
prep_kernel(const int* __restrict__ t32) {
    const int b = blockIdx.x;

    int bad = 0;
    for (int k = threadIdx.x; k < 32768; k += blockDim.x) {
        const int lo = t32[2 * k];
        const int hi = t32[2 * k + 1];
        const int want_hi = (lo < 0) ? -1 : 0;
        if (hi != want_hi || lo < -1 || lo >= V_) bad = 1;
    }
    const int any_bad = __syncthreads_or(bad);
    const int is64 = any_bad ? 0 : 1;

    // Count valid tokens (>= 0) in row b under the detected layout.
    const int stride = is64 ? 2 : 1;
    const int* row = t32 + (size_t)b * NT_ * stride;
    int cnt = 0;
    for (int i = threadIdx.x; i < NT_; i += blockDim.x)
        cnt += (row[i * stride] >= 0);

    #pragma unroll
    for (int off = 16; off > 0; off >>= 1)
        cnt += __shfl_down_sync(0xFFFFFFFFu, cnt, off);

    __shared__ int s_part[16];
    const int wid = threadIdx.x >> 5;
    const int lid = threadIdx.x & 31;
    if (lid == 0) s_part[wid] = cnt;
    __syncthreads();
    if (threadIdx.x == 0) {
        int total = 0;
        for (int w = 0; w < 16; ++w) total += s_part[w];
        g_len[b] = total;
        if (b == 0) g_is64 = is64;
    }
}

// ---------------------------------------------------------------------------
// Kernel 2: for each output row (b, p), map p -> source token index j via the
// stretch formula, gather emb[text[b,j]+1] (512 fp32 = 128 float4).
// grid = (NT, B), block = 128 threads, one float4 per thread.
// ---------------------------------------------------------------------------
__global__ void __launch_bounds__(D_VEC)
embed_stretch_kernel(const int* __restrict__ t32,
                     const float4* __restrict__ emb,
                     float4* __restrict__ out) {
    const int p = blockIdx.x;
    const int b = blockIdx.y;
    const int L = g_len[b];

    float4* dst = out + ((long long)b * NT_ + p) * D_VEC;

    if (L <= 0) {
        dst[threadIdx.x] = make_float4(0.f, 0.f, 0.f, 0.f);
        return;
    }

    const int base = NT_ / L;
    const int rem  = NT_ % L;
    const int boundary = (L - rem) * base;
    int j;
    if (p < boundary) j = p / base;
    else              j = (L - rem) + (p - boundary) / (base + 1);

    const long long flat = (long long)b * NT_ + j;
    int tok;
    if (g_is64) tok = t32[flat * 2] + 1;   // low word of little-endian int64
    else        tok = t32[flat] + 1;
    // Clamp: guarantees no OOB access under ANY interpretation.
    tok = min(max(tok, 0), V_);

    const float4* src = emb + (long long)tok * D_VEC;
    dst[threadIdx.x] = src[threadIdx.x];
}

// ---------------------------------------------------------------------------
// Launch. Identify inputs by element count:
//   text: 16*4096 = 65536 elements (int32 or int64-as-words = 131072)
//   emb : (2545+1)*512 = 1303552 fp32
//   seq_len: scalar (1 element) — value is always 4096, unused.
// ---------------------------------------------------------------------------
extern "C" void kernel_launch(void* const* d_in, const int* in_sizes, int n_in,
                              void* d_out, int out_size) {
    const int*   text = nullptr;
    const float* emb  = nullptr;
    for (int i = 0; i < n_in; ++i) {
        if (in_sizes[i] == B_ * NT_ || in_sizes[i] == 2 * B_ * NT_)
            text = (const int*)d_in[i];
        else if (in_sizes[i] == (V_ + 1) * D_)
            emb = (const float*)d_in[i];
    }

    prep_kernel<<<B_, 512>>>(text);

    dim3 grid(NT_, B_);
    embed_stretch_kernel<<<grid, D_VEC>>>(text, (const float4*)emb, (float4*)d_out);
    (void)out_size;
}

// round 3
// speedup vs baseline: 1.8560x; 1.8560x over previous
#include <cuda_runtime.h>
#include <cuda_bf16.h>
#include <stdint.h>

// Problem constants (fixed by reference: B=16, NT=4096, D=512, V=2545)
#define B_  16
#define NT_ 4096
#define D_  512
#define V_  2545
#define D_VEC (D_ / 4)          // 128 float4 per embedding row
#define NROWS (B_ * NT_)        // 65536 output rows

// Scratch (device allocations forbidden -> __device__ globals)
__device__ int g_tok[NROWS];    // precomputed source token (+1 applied); -1 => write zeros

// ---------------------------------------------------------------------------
// Prep kernel: one block per batch row b (16 blocks, 512 threads).
//  1) probe text dtype layout (int64 little-endian words vs int32) — each
//     block checks 256 word-pairs (always in bounds for either layout);
//     deterministic and identical across blocks.
//  2) count valid tokens L_b (token >= 0).
//  3) compute the stretch mapping j(p) for all p in [0,4096) and store
//     g_tok[b*4096+p] = text[b,j]+1  (or -1 if L_b == 0).
// ---------------------------------------------------------------------------
__global__ void __launch_bounds__(512)
prep_kernel(const int* __restrict__ t32) {
    const int b = blockIdx.x;

    // --- dtype probe (256 pairs, cheap, block-local identical result) ---
    int bad = 0;
    for (int k = threadIdx.x; k < 256; k += blockDim.x) {
        const int lo = t32[2 * k];
        const int hi = t32[2 * k + 1];
        const int want_hi = (lo < 0) ? -1 : 0;
        if (hi != want_hi || lo < -1 || lo >= V_) bad = 1;
    }
    const int is64 = __syncthreads_or(bad) ? 0 : 1;
    const int stride = is64 ? 2 : 1;

    // --- count valid tokens in row b ---
    const int* row = t32 + (size_t)b * NT_ * stride;
    int cnt = 0;
    for (int i = threadIdx.x; i < NT_; i += blockDim.x)
        cnt += (row[i * stride] >= 0);

    #pragma unroll
    for (int off = 16; off > 0; off >>= 1)
        cnt += __shfl_down_sync(0xFFFFFFFFu, cnt, off);

    __shared__ int s_part[16];
    const int wid = threadIdx.x >> 5;
    const int lid = threadIdx.x & 31;
    if (lid == 0) s_part[wid] = cnt;
    __syncthreads();
    __shared__ int s_L;
    if (threadIdx.x == 0) {
        int total = 0;
        for (int w = 0; w < 16; ++w) total += s_part[w];
        s_L = total;
    }
    __syncthreads();
    const int L = s_L;

    // --- stretch mapping + token fetch for all 4096 positions of row b ---
    if (L <= 0) {
        for (int p = threadIdx.x; p < NT_; p += blockDim.x)
            g_tok[b * NT_ + p] = -1;
        return;
    }
    const unsigned base = (unsigned)NT_ / (unsigned)L;
    const unsigned rem  = (unsigned)NT_ % (unsigned)L;
    const unsigned boundary = ((unsigned)L - rem) * base;

    for (int p = threadIdx.x; p < NT_; p += blockDim.x) {
        unsigned j;
        if ((unsigned)p < boundary) j = (unsigned)p / base;
        else                        j = ((unsigned)L - rem) + ((unsigned)p - boundary) / (base + 1);
        int tok = row[j * stride] + 1;          // in [1, V] for the valid prefix
        tok = min(max(tok, 0), V_);             // hard safety clamp
        g_tok[b * NT_ + p] = tok;
    }
}

// ---------------------------------------------------------------------------
// Embed kernel: pure gather-copy with MLP=4.
// 256 threads per block handle 8 rows: thread t owns lane = t & 127 of rows
// rowBase + (t>>7) + {0,2,4,6}. Four independent float4 loads are issued
// back-to-back, then four streaming stores.
// grid = NROWS / 8 = 8192 blocks.
// ---------------------------------------------------------------------------
__global__ void __launch_bounds__(256)
embed_copy_kernel(const float4* __restrict__ emb,
                  float4* __restrict__ out) {
    const int lane = threadIdx.x & 127;
    const int sub  = threadIdx.x >> 7;          // 0 or 1
    const int rowBase = blockIdx.x * 8 + sub;

    int tok[4];
    #pragma unroll
    for (int k = 0; k < 4; ++k)
        tok[k] = __ldg(&g_tok[rowBase + 2 * k]);

    float4 v[4];
    #pragma unroll
    for (int k = 0; k < 4; ++k) {
        if (tok[k] >= 0)
            v[k] = __ldg(emb + (long long)tok[k] * D_VEC + lane);
        else
            v[k] = make_float4(0.f, 0.f, 0.f, 0.f);
    }

    #pragma unroll
    for (int k = 0; k < 4; ++k)
        __stcs(out + (long long)(rowBase + 2 * k) * D_VEC + lane, v[k]);
}

// ---------------------------------------------------------------------------
// Launch. Identify inputs by element count:
//   text: 65536 elements (int32) or reported as 65536 with int64 storage,
//         or 131072 int32-words. The device-side probe resolves the layout.
//   emb : (2545+1)*512 = 1303552 fp32.
// ---------------------------------------------------------------------------
extern "C" void kernel_launch(void* const* d_in, const int* in_sizes, int n_in,
                              void* d_out, int out_size) {
    const int*   text = nullptr;
    const float* emb  = nullptr;
    for (int i = 0; i < n_in; ++i) {
        if (in_sizes[i] == NROWS || in_sizes[i] == 2 * NROWS)
            text = (const int*)d_in[i];
        else if (in_sizes[i] == (V_ + 1) * D_)
            emb = (const float*)d_in[i];
    }

    prep_kernel<<<B_, 512>>>(text);
    embed_copy_kernel<<<NROWS / 8, 256>>>((const float4*)emb, (float4*)d_out);
    (void)out_size;
}